// round 1
// baseline (speedup 1.0000x reference)
#include <cuda_runtime.h>
#include <math.h>

#define NQ      2048
#define ND      100000
#define DIM     16
#define THREADS 128
#define QPT     4
#define QBLK    (THREADS * QPT)   // 512 queries per block
#define QG      (NQ / QBLK)       // 4 query groups
#define TJ      128               // data points per smem tile
#define CHUNK   1408              // 11 tiles per chunk
#define CH      72                // 72 * 1408 = 101376 >= 100000
#define NPAD    (CH * CHUNK)
#define PREP_BLOCKS  148
#define PREP_THREADS 256

// Scratch (no allocations allowed -> __device__ globals)
__device__ float g_coeff[NPAD];          // w_j * exp(-0.5*||d_j||^2), zero-padded
__device__ float g_partials[CH * NQ];    // per-chunk partial sums
__device__ float g_wpart[PREP_BLOCKS];   // per-block partial sums of w

// ---------------------------------------------------------------------------
// Kernel 1: coeff_j = w_j * exp(-0.5 * ||d_j||^2); also block-partial sum of w
// ---------------------------------------------------------------------------
__global__ void kde_prep_kernel(const float* __restrict__ data,
                                const float* __restrict__ w) {
    int t = threadIdx.x;
    int bid = blockIdx.x;
    float wsum = 0.0f;
    for (int j = bid * PREP_THREADS + t; j < NPAD; j += PREP_BLOCKS * PREP_THREADS) {
        if (j < ND) {
            const float4* row = (const float4*)(data + (size_t)j * DIM);
            float dn = 0.0f;
#pragma unroll
            for (int v = 0; v < 4; v++) {
                float4 p = row[v];
                dn += p.x * p.x + p.y * p.y + p.z * p.z + p.w * p.w;
            }
            float wj = w[j];
            g_coeff[j] = wj * __expf(-0.5f * dn);
            wsum += wj;
        } else {
            g_coeff[j] = 0.0f;
        }
    }
    __shared__ float red[PREP_THREADS];
    red[t] = wsum;
    __syncthreads();
#pragma unroll
    for (int s = PREP_THREADS / 2; s > 0; s >>= 1) {
        if (t < s) red[t] += red[t + s];
        __syncthreads();
    }
    if (t == 0) g_wpart[bid] = red[0];
}

// ---------------------------------------------------------------------------
// Kernel 2: main pairwise loop.
//   grid = (QG, CH). Block (qg, ch): 512 queries (4/thread in regs),
//   streams its 1408-point chunk through a 128-point smem tile.
//   acc_q = sum_j coeff_j * exp(x_q . d_j)    (partial over this chunk)
// ---------------------------------------------------------------------------
__global__ __launch_bounds__(THREADS)
void kde_main_kernel(const float* __restrict__ X,
                     const float* __restrict__ data) {
    int t  = threadIdx.x;
    int qg = blockIdx.x;
    int ch = blockIdx.y;

    __shared__ float4 sd[TJ * 4];  // 128 points x 16 floats
    __shared__ float  sc[TJ];      // coeffs

    // Load 4 queries into registers
    float xq[QPT][DIM];
#pragma unroll
    for (int k = 0; k < QPT; k++) {
        int q = qg * QBLK + k * THREADS + t;
        const float4* row = (const float4*)(X + (size_t)q * DIM);
#pragma unroll
        for (int v = 0; v < 4; v++) {
            float4 p = row[v];
            xq[k][v * 4 + 0] = p.x;
            xq[k][v * 4 + 1] = p.y;
            xq[k][v * 4 + 2] = p.z;
            xq[k][v * 4 + 3] = p.w;
        }
    }

    float acc[QPT] = {0.0f, 0.0f, 0.0f, 0.0f};
    int j0 = ch * CHUNK;

    for (int tile = 0; tile < CHUNK; tile += TJ) {
        int base = j0 + tile;
        __syncthreads();  // protect previous tile's reads
        // Stage 128 points (512 float4) cooperatively
#pragma unroll
        for (int i = t; i < TJ * 4; i += THREADS) {
            int jj = base + (i >> 2);
            float4 v = make_float4(0.0f, 0.0f, 0.0f, 0.0f);
            if (jj < ND) v = ((const float4*)data)[(size_t)jj * 4 + (i & 3)];
            sd[i] = v;
        }
        sc[t] = g_coeff[base + t];  // TJ == THREADS, padded array covers OOB
        __syncthreads();

#pragma unroll 1
        for (int jj = 0; jj < TJ; jj++) {
            float dv[DIM];
#pragma unroll
            for (int v = 0; v < 4; v++) {
                float4 p = sd[jj * 4 + v];  // warp-broadcast LDS.128
                dv[v * 4 + 0] = p.x;
                dv[v * 4 + 1] = p.y;
                dv[v * 4 + 2] = p.z;
                dv[v * 4 + 3] = p.w;
            }
            float c = sc[jj];
            float dot0 = 0.0f, dot1 = 0.0f, dot2 = 0.0f, dot3 = 0.0f;
#pragma unroll
            for (int k = 0; k < DIM; k++) {
                dot0 = fmaf(dv[k], xq[0][k], dot0);
                dot1 = fmaf(dv[k], xq[1][k], dot1);
                dot2 = fmaf(dv[k], xq[2][k], dot2);
                dot3 = fmaf(dv[k], xq[3][k], dot3);
            }
            acc[0] = fmaf(c, __expf(dot0), acc[0]);
            acc[1] = fmaf(c, __expf(dot1), acc[1]);
            acc[2] = fmaf(c, __expf(dot2), acc[2]);
            acc[3] = fmaf(c, __expf(dot3), acc[3]);
        }
    }

#pragma unroll
    for (int k = 0; k < QPT; k++) {
        int q = qg * QBLK + k * THREADS + t;
        g_partials[(size_t)ch * NQ + q] = acc[k];
    }
}

// ---------------------------------------------------------------------------
// Kernel 3: finalize.
//   log_density[q] = log(S_q) - 0.5*||x_q||^2 - (d/2)*log(2*pi) - log(sum w)
//   All reductions in fixed order -> deterministic.
// ---------------------------------------------------------------------------
__global__ void kde_final_kernel(const float* __restrict__ X,
                                 float* __restrict__ out) {
    int q = blockIdx.x * blockDim.x + threadIdx.x;
    if (q >= NQ) return;

    float qn = 0.0f;
    const float4* row = (const float4*)(X + (size_t)q * DIM);
#pragma unroll
    for (int v = 0; v < 4; v++) {
        float4 p = row[v];
        qn += p.x * p.x + p.y * p.y + p.z * p.z + p.w * p.w;
    }

    float S = 0.0f;
#pragma unroll 8
    for (int ch = 0; ch < CH; ch++) S += g_partials[(size_t)ch * NQ + q];

    float sumw = 0.0f;
#pragma unroll 4
    for (int b = 0; b < PREP_BLOCKS; b++) sumw += g_wpart[b];

    const float LOG2PI = 1.8378770664093453f;
    out[q] = logf(S) - 0.5f * qn - 8.0f * LOG2PI - logf(sumw);
}

// ---------------------------------------------------------------------------
extern "C" void kernel_launch(void* const* d_in, const int* in_sizes, int n_in,
                              void* d_out, int out_size) {
    const float* X    = (const float*)d_in[0];  // [2048, 16]
    const float* data = (const float*)d_in[1];  // [100000, 16]
    const float* w    = (const float*)d_in[2];  // [100000]
    float* out = (float*)d_out;                 // [2048]

    kde_prep_kernel<<<PREP_BLOCKS, PREP_THREADS>>>(data, w);
    kde_main_kernel<<<dim3(QG, CH), THREADS>>>(X, data);
    kde_final_kernel<<<(NQ + 255) / 256, 256>>>(X, out);
}